// round 3
// baseline (speedup 1.0000x reference)
#include <cuda_runtime.h>
#include <math.h>
#include <stdint.h>

#define THREADS 256

// ---------------- layer tables ----------------
__constant__ int d_H[5]        = {480, 240, 120, 60, 30};
__constant__ int d_chanBase[5] = {0, 64, 192, 448, 960};

// ---------------- scratch (device globals; no allocation) ----------------
__device__ unsigned      g_cstat[1472][2];   // per-channel min/max (encoded)
__device__ int           g_hist[1472][12];   // [0:6) bin hist, [6:12) gidx hist
__device__ float         g_lut[1472][8];     // per-channel contribution LUT (6 used)
__device__ float         g_border[5];        // proc value at border pixels per layer
__device__ unsigned char g_gidx[28108800];   // per-pixel gidx bytes
__device__ float         g_proc[306900];     // per-layer proc maps (then thresholded)
__device__ unsigned      g_pstat[5][2];      // proc min/max per layer
__device__ float         g_group[5][57600];  // resized maps
__device__ unsigned      g_gstat[5][2];      // group min/max per layer

// ---------------- float <-> orderable uint ----------------
__device__ __forceinline__ unsigned fenc(float f) {
    unsigned b = __float_as_uint(f);
    return (b & 0x80000000u) ? ~b : (b | 0x80000000u);
}
__device__ __forceinline__ float fdec(unsigned u) {
    unsigned b = (u & 0x80000000u) ? (u & 0x7FFFFFFFu) : ~u;
    return __uint_as_float(b);
}

// block min/max reduce into encoded-uint stats; s = shared scratch (>=16 floats)
__device__ __forceinline__ void blockMinMax(float vmn, float vmx, unsigned* stat, float* s) {
#pragma unroll
    for (int o = 16; o; o >>= 1) {
        vmn = fminf(vmn, __shfl_xor_sync(0xFFFFFFFFu, vmn, o));
        vmx = fmaxf(vmx, __shfl_xor_sync(0xFFFFFFFFu, vmx, o));
    }
    int w = threadIdx.x >> 5;
    if ((threadIdx.x & 31) == 0) { s[w] = vmn; s[8 + w] = vmx; }
    __syncthreads();
    if (threadIdx.x == 0) {
        float a = s[0], b = s[8];
#pragma unroll
        for (int i = 1; i < 8; i++) { a = fminf(a, s[i]); b = fmaxf(b, s[8 + i]); }
        atomicMin(&stat[0], fenc(a));
        atomicMax(&stat[1], fenc(b));
    }
    __syncthreads();
}

// ---------------- pass 0: init ----------------
__global__ void __launch_bounds__(THREADS) k_init() {
    int i = blockIdx.x * THREADS + threadIdx.x;
    if (i < 1472 * 12) ((int*)g_hist)[i] = 0;
    if (i < 1472) { g_cstat[i][0] = 0xFFFFFFFFu; g_cstat[i][1] = 0u; }
    if (i < 5) {
        g_pstat[i][0] = 0xFFFFFFFFu; g_pstat[i][1] = 0u;
        g_gstat[i][0] = 0xFFFFFFFFu; g_gstat[i][1] = 0u;
    }
}

// ---------------- block decode for passes A/B ----------------
// tiles per channel: {16,4,1,1,1}; blocks per layer {1024,512,256,512,512}; total 2816
struct BlkInfo { int layer, cloc, tile; };
__device__ __forceinline__ BlkInfo decodeAB(int b) {
    BlkInfo r;
    if (b < 1024)      { r.layer = 0; r.cloc = b >> 4;            r.tile = b & 15; }
    else if (b < 1536) { int t = b - 1024; r.layer = 1; r.cloc = t >> 2; r.tile = t & 3; }
    else if (b < 1792) { r.layer = 2; r.cloc = b - 1536; r.tile = 0; }
    else if (b < 2304) { r.layer = 3; r.cloc = b - 1792; r.tile = 0; }
    else               { r.layer = 4; r.cloc = b - 2304; r.tile = 0; }
    return r;
}

// ---------------- pass A: per-channel interior min/max (border zeros included) ----------------
template <int H, int T>
__device__ __forceinline__ void mm_body(const float* __restrict__ base, int tile,
                                        float& omn, float& omx) {
    constexpr int W = H;
    float mn = 0.f, mx = 0.f;  // border zeros always present in the bordered channel
    for (int r = 1 + tile; r < H - 1; r += T) {
        const float* row = base + r * W;
        for (int c = 1 + threadIdx.x; c < W - 1; c += THREADS) {
            float v = row[c];
            mn = fminf(mn, v); mx = fmaxf(mx, v);
        }
    }
    omn = mn; omx = mx;
}

__global__ void __launch_bounds__(THREADS) k_minmax(const float* __restrict__ p0, const float* __restrict__ p1,
                                                    const float* __restrict__ p2, const float* __restrict__ p3,
                                                    const float* __restrict__ p4) {
    __shared__ float sred[16];
    BlkInfo bi = decodeAB(blockIdx.x);
    float mn = 0.f, mx = 0.f;
    int ch;
    switch (bi.layer) {
        case 0: ch = bi.cloc;       mm_body<480, 16>(p0 + (long long)bi.cloc * 230400, bi.tile, mn, mx); break;
        case 1: ch = 64 + bi.cloc;  mm_body<240, 4>(p1 + (long long)bi.cloc * 57600, bi.tile, mn, mx); break;
        case 2: ch = 192 + bi.cloc; mm_body<120, 1>(p2 + (long long)bi.cloc * 14400, bi.tile, mn, mx); break;
        case 3: ch = 448 + bi.cloc; mm_body<60, 1>(p3 + (long long)bi.cloc * 3600, bi.tile, mn, mx); break;
        default: ch = 960 + bi.cloc; mm_body<30, 1>(p4 + (long long)bi.cloc * 900, bi.tile, mn, mx); break;
    }
    blockMinMax(mn, mx, g_cstat[ch], sred);
}

// ---------------- pass B: dual histograms + gidx byte store ----------------
__device__ __forceinline__ void bin_pair(float v, float mn, float rng, bool zr, int& b1, int& b2) {
    float d = zr ? 0.f : __fdiv_rn(v - mn, rng);
    float nrm = __fmul_rn(d, 256.f);
    float q1 = __fdiv_rn(nrm, 42.666668f);          // 256/6 rounded to f32
    b1 = (int)floorf(q1); b1 = max(0, min(5, b1));
    float q2 = __fadd_rn(__fmul_rn(nrm, 6.f), -1.f);
    b2 = (int)q2; b2 = max(0, min(5, b2));          // trunc toward zero, then clip
}

template <int H, int T>
__device__ void hist_body(const float* __restrict__ base, int tile, int ch,
                          unsigned char* __restrict__ gout) {
    constexpr int W = H;
    float mn = fdec(g_cstat[ch][0]);
    float mx = fdec(g_cstat[ch][1]);
    float rng = mx - mn;
    bool zr = (rng == 0.f);
    unsigned long long h1 = 0ULL, h2 = 0ULL;   // 6x 10-bit packed counters (max 118 < 1023)
    for (int r = 1 + tile; r < H - 1; r += T) {
        const float* row = base + r * W;
        unsigned char* grow = gout + r * W;
        for (int c = 1 + threadIdx.x; c < W - 1; c += THREADS) {
            int b1, b2;
            bin_pair(row[c], mn, rng, zr, b1, b2);
            grow[c] = (unsigned char)b2;
            h1 += 1ULL << (b1 * 10);
            h2 += 1ULL << (b2 * 10);
        }
    }
#pragma unroll
    for (int j = 0; j < 6; j++) {
        int c1 = (int)((h1 >> (j * 10)) & 1023u);
        int c2 = (int)((h2 >> (j * 10)) & 1023u);
        c1 = __reduce_add_sync(0xFFFFFFFFu, c1);
        c2 = __reduce_add_sync(0xFFFFFFFFu, c2);
        if ((threadIdx.x & 31) == 0) {
            if (c1) atomicAdd(&g_hist[ch][j], c1);
            if (c2) atomicAdd(&g_hist[ch][6 + j], c2);
        }
    }
    if (tile == 0 && threadIdx.x == 0) {       // border pixels: value exactly 0, all identical
        int b1, b2;
        bin_pair(0.f, mn, rng, zr, b1, b2);
        int Nb = 2 * (H + W) - 4;
        atomicAdd(&g_hist[ch][b1], Nb);
        atomicAdd(&g_hist[ch][6 + b2], Nb);
    }
}

__global__ void __launch_bounds__(THREADS) k_hist(const float* __restrict__ p0, const float* __restrict__ p1,
                                                  const float* __restrict__ p2, const float* __restrict__ p3,
                                                  const float* __restrict__ p4) {
    BlkInfo bi = decodeAB(blockIdx.x);
    switch (bi.layer) {
        case 0: hist_body<480, 16>(p0 + (long long)bi.cloc * 230400, bi.tile, bi.cloc,
                                   g_gidx + (long long)bi.cloc * 230400); break;
        case 1: hist_body<240, 4>(p1 + (long long)bi.cloc * 57600, bi.tile, 64 + bi.cloc,
                                  g_gidx + 14745600LL + (long long)bi.cloc * 57600); break;
        case 2: hist_body<120, 1>(p2 + (long long)bi.cloc * 14400, bi.tile, 192 + bi.cloc,
                                  g_gidx + 22118400LL + (long long)bi.cloc * 14400); break;
        case 3: hist_body<60, 1>(p3 + (long long)bi.cloc * 3600, bi.tile, 448 + bi.cloc,
                                 g_gidx + 25804800LL + (long long)bi.cloc * 3600); break;
        default: hist_body<30, 1>(p4 + (long long)bi.cloc * 900, bi.tile, 960 + bi.cloc,
                                  g_gidx + 27648000LL + (long long)bi.cloc * 900); break;
    }
}

// ---------------- pass LUT: per-channel 6-entry contribution table ----------------
__global__ void __launch_bounds__(THREADS) k_lut() {
    int ch = blockIdx.x * THREADS + threadIdx.x;
    if (ch >= 1472) return;
    int layer = ch < 64 ? 0 : ch < 192 ? 1 : ch < 448 ? 2 : ch < 960 ? 3 : 4;
    int H = d_H[layer], W = H;
    float Nf = (float)(H * W);
    float mn = fdec(g_cstat[ch][0]);
    float mx = fdec(g_cstat[ch][1]);
    float rng = mx - mn;
    bool zr = (rng == 0.f);

    float hv[6]; int gg[6];
#pragma unroll
    for (int j = 0; j < 6; j++) {
        hv[j] = -logf(__fdiv_rn((float)g_hist[ch][j], Nf) + 1e-4f);
        gg[j] = g_hist[ch][6 + j];
    }
    float minv = 1e30f, maxv = -1e30f;
#pragma unroll
    for (int j = 0; j < 6; j++)
        if (gg[j] > 0) { minv = fminf(minv, hv[j]); maxv = fmaxf(maxv, hv[j]); }
    float rh = maxv - minv;

    // border bin (value exactly 0)
    int b1b, jb;
    bin_pair(0.f, mn, rng, zr, b1b, jb);
    bool first = (ch == d_chanBase[layer]);   // channel 0 keeps its border in the map

    float lut[6] = {0.f, 0.f, 0.f, 0.f, 0.f, 0.f};
    if (rh > 0.f) {
        float dn[6];
#pragma unroll
        for (int j = 0; j < 6; j++)
            dn[j] = (gg[j] > 0) ? __fdiv_rn(hv[j] - minv, rh) : 0.f;
        float meandn = 0.f;
#pragma unroll
        for (int j = 0; j < 6; j++) meandn += (float)gg[j] * dn[j];
        meandn = __fdiv_rn(meandn, Nf);
        float w1 = 1.f - meandn; w1 *= w1;     // (max_dst - mean_dst)^2, max_dst == 1
        int Nb = 2 * (H + W) - 4;
        float mean_m = 0.f;
        float max_m = first ? -1e30f : 0.f;    // zeroed border contributes value 0 for c>=1
#pragma unroll
        for (int j = 0; j < 6; j++) {
            int cnt = gg[j] - ((!first && j == jb) ? Nb : 0);
            float rv = dn[j] * w1;
            if (cnt > 0) { mean_m += (float)cnt * rv; max_m = fmaxf(max_m, rv); }
        }
        mean_m = __fdiv_rn(mean_m, Nf);
        if (max_m > 0.f) {
            float w2 = max_m - mean_m; w2 *= w2;   // min_m == 0 always
#pragma unroll
            for (int j = 0; j < 6; j++)
                lut[j] = __fmul_rn(__fdiv_rn(dn[j] * w1, max_m), w2);
        }
    }
#pragma unroll
    for (int j = 0; j < 6; j++) g_lut[ch][j] = lut[j];
    g_lut[ch][6] = 0.f; g_lut[ch][7] = 0.f;
    if (first) g_border[layer] = lut[jb];
}

// ---------------- pass C: proc = sum_c lut_c[gidx_c] ; proc min/max ----------------
template <int LAYER, int H, int C, int CB, long long GB, int PB>
__device__ void proc_body(int blk0, float (*slut)[8], float* sred) {
    constexpr int W = H, HW = H * W;
    const float* src = &g_lut[CB][0];
    for (int i = threadIdx.x; i < C * 8; i += THREADS) ((float*)slut)[i] = src[i];
    __syncthreads();
    float bord = g_border[LAYER];
    int p = blk0 * THREADS + threadIdx.x;
    float val = bord;
    if (p < HW) {
        int r = p / W, c = p % W;
        if (r > 0 && c > 0 && r < H - 1 && c < W - 1) {
            float s = 0.f;
            const unsigned char* gp = g_gidx + GB + p;
#pragma unroll 4
            for (int ch = 0; ch < C; ch++) s += slut[ch][gp[(long long)ch * HW]];
            val = s;
        }
        g_proc[PB + p] = val;
    }
    blockMinMax(fminf(val, bord), fmaxf(val, bord), g_pstat[LAYER], sred);
}

__global__ void __launch_bounds__(THREADS) k_proc() {
    __shared__ float slut[512][8];
    __shared__ float sred[16];
    int b = blockIdx.x;
    if (b < 900)       proc_body<0, 480, 64, 0, 0LL, 0>(b, slut, sred);
    else if (b < 1125) proc_body<1, 240, 128, 64, 14745600LL, 230400>(b - 900, slut, sred);
    else if (b < 1182) proc_body<2, 120, 256, 192, 22118400LL, 288000>(b - 1125, slut, sred);
    else if (b < 1197) proc_body<3, 60, 512, 448, 25804800LL, 302400>(b - 1182, slut, sred);
    else               proc_body<4, 30, 512, 960, 27648000LL, 306000>(b - 1197, slut, sred);
}

// ---------------- pass D: normalize proc + threshold (in place) ----------------
__global__ void __launch_bounds__(THREADS) k_thresh() {
    int i = blockIdx.x * THREADS + threadIdx.x;
    if (i >= 306900) return;
    int layer = i < 230400 ? 0 : i < 288000 ? 1 : i < 302400 ? 2 : i < 306000 ? 3 : 4;
    float mnp = fdec(g_pstat[layer][0]);
    float mxp = fdec(g_pstat[layer][1]);
    float rng = mxp - mnp;
    float v = g_proc[i];
    float pn = (rng == 0.f) ? 0.f : __fdiv_rn(v - mnp, rng);
    g_proc[i] = (pn < 0.2f) ? 0.f : pn;
}

// ---------------- pass E: resize to 240x240 per layer + group min/max ----------------
__global__ void __launch_bounds__(THREADS) k_resize() {
    __shared__ float sred[16];
    int b = blockIdx.x;
    int layer = b / 225;
    int p = (b - layer * 225) * THREADS + threadIdx.x;   // < 57600 exactly
    int y = p / 240, x = p % 240;
    float val;
    if (layer == 0) {
        // 480 -> 240 antialiased: taps [1,3,3,1]/8, edge-renormalized
        const float w4[4] = {1.f, 3.f, 3.f, 1.f};
        float wxs = 0.f;
#pragma unroll
        for (int j = 0; j < 4; j++) { int tx = 2 * x - 1 + j; if (tx >= 0 && tx < 480) wxs += w4[j]; }
        float acc = 0.f, wys = 0.f;
#pragma unroll
        for (int a = 0; a < 4; a++) {
            int ty = 2 * y - 1 + a;
            if (ty < 0 || ty > 479) continue;
            wys += w4[a];
            const float* row = g_proc + ty * 480;
            float ra = 0.f;
#pragma unroll
            for (int j = 0; j < 4; j++) {
                int tx = 2 * x - 1 + j;
                if (tx >= 0 && tx < 480) ra += w4[j] * row[tx];
            }
            acc += w4[a] * ra;
        }
        val = acc / (wys * wxs);
    } else if (layer == 1) {
        val = g_proc[230400 + p];                        // identity
    } else {
        int H = layer == 2 ? 120 : layer == 3 ? 60 : 30;
        int base = layer == 2 ? 288000 : layer == 3 ? 302400 : 306000;
        const float* pr = g_proc + base;
        float s = (float)H / 240.f;                      // 0.5 / 0.25 / 0.125 exact
        float cy = (y + 0.5f) * s - 0.5f;
        float cx = (x + 0.5f) * s - 0.5f;
        float fly = floorf(cy), flx = floorf(cx);
        float fy = cy - fly, fx = cx - flx;
        int iy = (int)fly, ix = (int)flx;
        int y0 = max(iy, 0), y1 = min(iy + 1, H - 1);
        int x0 = max(ix, 0), x1 = min(ix + 1, H - 1);
        float a = pr[y0 * H + x0], bv = pr[y0 * H + x1];
        float c = pr[y1 * H + x0], d = pr[y1 * H + x1];
        val = (1.f - fy) * ((1.f - fx) * a + fx * bv) + fy * ((1.f - fx) * c + fx * d);
    }
    g_group[layer][p] = val;
    blockMinMax(val, val, g_gstat[layer], sred);
}

// ---------------- pass F: group normalize(0,256), write groups + sum ----------------
__global__ void __launch_bounds__(THREADS) k_final(float* __restrict__ out, int out_size) {
    int p = blockIdx.x * THREADS + threadIdx.x;          // 225 blocks * 256 = 57600 exactly
    float s = 0.f;
#pragma unroll
    for (int g = 0; g < 5; g++) {
        float mn = fdec(g_gstat[g][0]);
        float mx = fdec(g_gstat[g][1]);
        float rng = mx - mn;
        float v = g_group[g][p];
        float gv = (rng == 0.f) ? 0.f : __fmul_rn(__fdiv_rn(v - mn, rng), 256.f);
        if (out_size >= 345600) out[57600 + p * 5 + g] = gv;
        s += gv;
    }
    out[p] = s;
}

// ---------------- launch ----------------
extern "C" void kernel_launch(void* const* d_in, const int* in_sizes, int n_in,
                              void* d_out, int out_size) {
    // map inputs by element count (robust to ordering)
    const int want[5] = {14745600, 7372800, 3686400, 1843200, 460800};
    const float* L[5] = {nullptr, nullptr, nullptr, nullptr, nullptr};
    for (int i = 0; i < n_in && i < 16; i++)
        for (int j = 0; j < 5; j++)
            if (in_sizes[i] == want[j] && L[j] == nullptr) { L[j] = (const float*)d_in[i]; break; }
    for (int j = 0; j < 5; j++) if (!L[j] && j < n_in) L[j] = (const float*)d_in[j];

    k_init<<<69, THREADS>>>();
    k_minmax<<<2816, THREADS>>>(L[0], L[1], L[2], L[3], L[4]);
    k_hist<<<2816, THREADS>>>(L[0], L[1], L[2], L[3], L[4]);
    k_lut<<<6, THREADS>>>();
    k_proc<<<1201, THREADS>>>();
    k_thresh<<<1199, THREADS>>>();
    k_resize<<<1125, THREADS>>>();
    k_final<<<225, THREADS>>>((float*)d_out, out_size);
}

// round 4
// speedup vs baseline: 1.0840x; 1.0840x over previous
#include <cuda_runtime.h>
#include <math.h>
#include <stdint.h>

#define THREADS 256

// ---------------- layer tables ----------------
__constant__ int d_H[5]        = {480, 240, 120, 60, 30};
__constant__ int d_chanBase[5] = {0, 64, 192, 448, 960};

// ---------------- scratch (device globals; no allocation) ----------------
__device__ unsigned      g_cstat[1472][2];   // per-channel min/max (encoded)
__device__ int           g_hist[1472][12];   // [0:6) bin hist, [6:12) gidx hist
__device__ float         g_dlut[1472][8];    // [0:6)=lut[b]-lut[5], [6]=lut[5], [7]=0
__device__ float         g_border[5];        // proc value at border pixels per layer
__device__ unsigned char g_gidx[28108800];   // per-pixel gidx bytes
__device__ float         g_proc[306900];     // per-layer proc maps (raw, pre-threshold)
__device__ unsigned      g_pstat[5][2];      // proc min/max per layer
__device__ float         g_group[5][57600];  // resized+thresholded maps
__device__ unsigned      g_gstat[5][2];      // group min/max per layer

// ---------------- float <-> orderable uint ----------------
__device__ __forceinline__ unsigned fenc(float f) {
    unsigned b = __float_as_uint(f);
    return (b & 0x80000000u) ? ~b : (b | 0x80000000u);
}
__device__ __forceinline__ float fdec(unsigned u) {
    unsigned b = (u & 0x80000000u) ? (u & 0x7FFFFFFFu) : ~u;
    return __uint_as_float(b);
}

__device__ __forceinline__ void blockMinMax(float vmn, float vmx, unsigned* stat, float* s) {
#pragma unroll
    for (int o = 16; o; o >>= 1) {
        vmn = fminf(vmn, __shfl_xor_sync(0xFFFFFFFFu, vmn, o));
        vmx = fmaxf(vmx, __shfl_xor_sync(0xFFFFFFFFu, vmx, o));
    }
    int w = threadIdx.x >> 5;
    if ((threadIdx.x & 31) == 0) { s[w] = vmn; s[8 + w] = vmx; }
    __syncthreads();
    if (threadIdx.x == 0) {
        float a = s[0], b = s[8];
#pragma unroll
        for (int i = 1; i < 8; i++) { a = fminf(a, s[i]); b = fmaxf(b, s[8 + i]); }
        atomicMin(&stat[0], fenc(a));
        atomicMax(&stat[1], fenc(b));
    }
    __syncthreads();
}

// ---------------- shared binning coefficients (must be identical in hist & lut) ----
__device__ __forceinline__ void make_coeffs(float mn, float mx,
                                            float& sA, float& cA, float& sB, float& cB) {
    float rng = mx - mn;
    if (rng == 0.f) { sA = 0.f; cA = 0.f; sB = 0.f; cB = -1.f; }
    else {
        sA = __fdiv_rn(6.f, rng);    cA = __fmul_rn(-mn, sA);
        sB = __fdiv_rn(1536.f, rng); cB = __fmaf_rn(-mn, sB, -1.f);
    }
}
__device__ __forceinline__ void bin_of(float v, float sA, float cA, float sB, float cB,
                                       int& b1, int& b2) {
    b1 = __float2int_rd(__fmaf_rn(v, sA, cA)); b1 = max(0, min(5, b1));
    b2 = __float2int_rz(__fmaf_rn(v, sB, cB)); b2 = max(0, min(5, b2));
}

// ---------------- pass 0: init ----------------
__global__ void __launch_bounds__(THREADS) k_init() {
    int i = blockIdx.x * THREADS + threadIdx.x;
    if (i < 1472 * 12) ((int*)g_hist)[i] = 0;
    if (i < 1472) { g_cstat[i][0] = 0xFFFFFFFFu; g_cstat[i][1] = 0u; }
    if (i < 5) {
        g_pstat[i][0] = 0xFFFFFFFFu; g_pstat[i][1] = 0u;
        g_gstat[i][0] = 0xFFFFFFFFu; g_gstat[i][1] = 0u;
    }
}

// ---------------- block decode for passes A/B ----------------
// tiles per channel: {16,4,1,1,1}; blocks per layer {1024,512,256,512,512}; total 2816
struct BlkInfo { int layer, cloc, tile; };
__device__ __forceinline__ BlkInfo decodeAB(int b) {
    BlkInfo r;
    if (b < 1024)      { r.layer = 0; r.cloc = b >> 4;            r.tile = b & 15; }
    else if (b < 1536) { int t = b - 1024; r.layer = 1; r.cloc = t >> 2; r.tile = t & 3; }
    else if (b < 1792) { r.layer = 2; r.cloc = b - 1536; r.tile = 0; }
    else if (b < 2304) { r.layer = 3; r.cloc = b - 1792; r.tile = 0; }
    else               { r.layer = 4; r.cloc = b - 2304; r.tile = 0; }
    return r;
}

// ---------------- pass A: per-channel min/max ----------------
// vector body: interior rows, full rows as float4, border cols masked to 0
template <int H, int T>
__device__ __forceinline__ void mmv_body(const float* __restrict__ base, int tile,
                                         float& omn, float& omx) {
    constexpr int W = H, F4 = W / 4;
    int rowsThis = (H - 2 - tile + T - 1) / T;
    int total = rowsThis * F4;
    float mn = 0.f, mx = 0.f;  // border zeros always present
    for (int i = threadIdx.x; i < total; i += THREADS) {
        int m = i / F4, j = i - m * F4;
        int r = 1 + tile + m * T;
        float4 v = *(const float4*)(base + r * W + 4 * j);
        if (j == 0) v.x = 0.f;
        if (j == F4 - 1) v.w = 0.f;
        mn = fminf(mn, fminf(fminf(v.x, v.y), fminf(v.z, v.w)));
        mx = fmaxf(mx, fmaxf(fmaxf(v.x, v.y), fmaxf(v.z, v.w)));
    }
    omn = mn; omx = mx;
}
// scalar body (layer 4, W=30, rows not 16B-aligned)
template <int H>
__device__ __forceinline__ void mms_body(const float* __restrict__ base,
                                         float& omn, float& omx) {
    constexpr int W = H, IW = W - 2, NI = IW * (H - 2);
    float mn = 0.f, mx = 0.f;
    for (int i = threadIdx.x; i < NI; i += THREADS) {
        int q = i / IW, col = i - q * IW;
        float v = base[(q + 1) * W + col + 1];
        mn = fminf(mn, v); mx = fmaxf(mx, v);
    }
    omn = mn; omx = mx;
}

__global__ void __launch_bounds__(THREADS) k_minmax(const float* __restrict__ p0, const float* __restrict__ p1,
                                                    const float* __restrict__ p2, const float* __restrict__ p3,
                                                    const float* __restrict__ p4) {
    __shared__ float sred[16];
    BlkInfo bi = decodeAB(blockIdx.x);
    float mn = 0.f, mx = 0.f;
    int ch;
    switch (bi.layer) {
        case 0: ch = bi.cloc;       mmv_body<480, 16>(p0 + (long long)bi.cloc * 230400, bi.tile, mn, mx); break;
        case 1: ch = 64 + bi.cloc;  mmv_body<240, 4>(p1 + (long long)bi.cloc * 57600, bi.tile, mn, mx); break;
        case 2: ch = 192 + bi.cloc; mmv_body<120, 1>(p2 + (long long)bi.cloc * 14400, bi.tile, mn, mx); break;
        case 3: ch = 448 + bi.cloc; mmv_body<60, 1>(p3 + (long long)bi.cloc * 3600, bi.tile, mn, mx); break;
        default: ch = 960 + bi.cloc; mms_body<30>(p4 + (long long)bi.cloc * 900, mn, mx); break;
    }
    blockMinMax(mn, mx, g_cstat[ch], sred);
}

// ---------------- pass B: dual histograms + gidx byte store ----------------
__device__ __forceinline__ void hist_flush(unsigned long long h1, unsigned long long h2, int ch) {
#pragma unroll
    for (int j = 0; j < 6; j++) {
        int c1 = (int)((h1 >> (j * 10)) & 1023u);
        int c2 = (int)((h2 >> (j * 10)) & 1023u);
        c1 = __reduce_add_sync(0xFFFFFFFFu, c1);
        c2 = __reduce_add_sync(0xFFFFFFFFu, c2);
        if ((threadIdx.x & 31) == 0) {
            if (c1) atomicAdd(&g_hist[ch][j], c1);
            if (c2) atomicAdd(&g_hist[ch][6 + j], c2);
        }
    }
}

template <int H, int T>
__device__ void histv_body(const float* __restrict__ base, int tile, int ch,
                           unsigned char* __restrict__ gout) {
    constexpr int W = H, F4 = W / 4;
    float mn = fdec(g_cstat[ch][0]);
    float mx = fdec(g_cstat[ch][1]);
    float sA, cA, sB, cB;
    make_coeffs(mn, mx, sA, cA, sB, cB);
    unsigned long long h1 = 0ULL, h2 = 0ULL;   // 6x 10-bit packed (max px/thread 60)
    int rowsThis = (H - 2 - tile + T - 1) / T;
    int total = rowsThis * F4;
    for (int i = threadIdx.x; i < total; i += THREADS) {
        int m = i / F4, j = i - m * F4;
        int r = 1 + tile + m * T;
        float4 v = *(const float4*)(base + r * W + 4 * j);
        if (j == 0) v.x = 0.f;
        if (j == F4 - 1) v.w = 0.f;
        unsigned pack = 0;
#pragma unroll
        for (int k = 0; k < 4; k++) {
            float vk = (&v.x)[k];
            int b1, b2;
            bin_of(vk, sA, cA, sB, cB, b1, b2);
            h1 += 1ULL << (b1 * 10);
            h2 += 1ULL << (b2 * 10);
            pack |= (unsigned)b2 << (8 * k);
        }
        *(unsigned*)(gout + r * W + 4 * j) = pack;
    }
    hist_flush(h1, h2, ch);
    if (tile == 0 && threadIdx.x == 0) {       // rows 0 & H-1 (value exactly 0)
        int b1, b2;
        bin_of(0.f, sA, cA, sB, cB, b1, b2);
        atomicAdd(&g_hist[ch][b1], 2 * W);
        atomicAdd(&g_hist[ch][6 + b2], 2 * W);
    }
}

template <int H>
__device__ void hists_body(const float* __restrict__ base, int ch,
                           unsigned char* __restrict__ gout) {
    constexpr int W = H, IW = W - 2, NI = IW * (H - 2);
    float mn = fdec(g_cstat[ch][0]);
    float mx = fdec(g_cstat[ch][1]);
    float sA, cA, sB, cB;
    make_coeffs(mn, mx, sA, cA, sB, cB);
    unsigned long long h1 = 0ULL, h2 = 0ULL;
    for (int i = threadIdx.x; i < NI; i += THREADS) {
        int q = i / IW, col = i - q * IW;
        int pix = (q + 1) * W + col + 1;
        int b1, b2;
        bin_of(base[pix], sA, cA, sB, cB, b1, b2);
        gout[pix] = (unsigned char)b2;
        h1 += 1ULL << (b1 * 10);
        h2 += 1ULL << (b2 * 10);
    }
    hist_flush(h1, h2, ch);
    if (threadIdx.x == 0) {                    // full border: 2(H+W)-4 zero px
        int b1, b2;
        bin_of(0.f, sA, cA, sB, cB, b1, b2);
        int Nb = 2 * (H + W) - 4;
        atomicAdd(&g_hist[ch][b1], Nb);
        atomicAdd(&g_hist[ch][6 + b2], Nb);
    }
}

__global__ void __launch_bounds__(THREADS) k_hist(const float* __restrict__ p0, const float* __restrict__ p1,
                                                  const float* __restrict__ p2, const float* __restrict__ p3,
                                                  const float* __restrict__ p4) {
    BlkInfo bi = decodeAB(blockIdx.x);
    switch (bi.layer) {
        case 0: histv_body<480, 16>(p0 + (long long)bi.cloc * 230400, bi.tile, bi.cloc,
                                    g_gidx + (long long)bi.cloc * 230400); break;
        case 1: histv_body<240, 4>(p1 + (long long)bi.cloc * 57600, bi.tile, 64 + bi.cloc,
                                   g_gidx + 14745600LL + (long long)bi.cloc * 57600); break;
        case 2: histv_body<120, 1>(p2 + (long long)bi.cloc * 14400, bi.tile, 192 + bi.cloc,
                                   g_gidx + 22118400LL + (long long)bi.cloc * 14400); break;
        case 3: histv_body<60, 1>(p3 + (long long)bi.cloc * 3600, bi.tile, 448 + bi.cloc,
                                  g_gidx + 25804800LL + (long long)bi.cloc * 3600); break;
        default: hists_body<30>(p4 + (long long)bi.cloc * 900, 960 + bi.cloc,
                                g_gidx + 27648000LL + (long long)bi.cloc * 900); break;
    }
}

// ---------------- pass LUT: per-channel 6-entry contribution table ----------------
__global__ void __launch_bounds__(THREADS) k_lut() {
    int ch = blockIdx.x * THREADS + threadIdx.x;
    if (ch >= 1472) return;
    int layer = ch < 64 ? 0 : ch < 192 ? 1 : ch < 448 ? 2 : ch < 960 ? 3 : 4;
    int H = d_H[layer], W = H;
    float Nf = (float)(H * W);
    float mn = fdec(g_cstat[ch][0]);
    float mx = fdec(g_cstat[ch][1]);
    float sA, cA, sB, cB;
    make_coeffs(mn, mx, sA, cA, sB, cB);

    float hv[6]; int gg[6];
#pragma unroll
    for (int j = 0; j < 6; j++) {
        hv[j] = -logf(__fdiv_rn((float)g_hist[ch][j], Nf) + 1e-4f);
        gg[j] = g_hist[ch][6 + j];
    }
    float minv = 1e30f, maxv = -1e30f;
#pragma unroll
    for (int j = 0; j < 6; j++)
        if (gg[j] > 0) { minv = fminf(minv, hv[j]); maxv = fmaxf(maxv, hv[j]); }
    float rh = maxv - minv;

    int b1b, jb;
    bin_of(0.f, sA, cA, sB, cB, b1b, jb);     // bin of the (zero) border pixels
    bool first = (ch == d_chanBase[layer]);   // channel 0 keeps its border in the map

    float lut[6] = {0.f, 0.f, 0.f, 0.f, 0.f, 0.f};
    if (rh > 0.f) {
        float dn[6];
#pragma unroll
        for (int j = 0; j < 6; j++)
            dn[j] = (gg[j] > 0) ? __fdiv_rn(hv[j] - minv, rh) : 0.f;
        float meandn = 0.f;
#pragma unroll
        for (int j = 0; j < 6; j++) meandn += (float)gg[j] * dn[j];
        meandn = __fdiv_rn(meandn, Nf);
        float w1 = 1.f - meandn; w1 *= w1;     // (max_dst - mean_dst)^2, max_dst == 1
        int Nb = 2 * (H + W) - 4;
        float mean_m = 0.f;
        float max_m = first ? -1e30f : 0.f;    // zeroed border contributes 0 for c>=1
#pragma unroll
        for (int j = 0; j < 6; j++) {
            int cnt = gg[j] - ((!first && j == jb) ? Nb : 0);
            float rv = dn[j] * w1;
            if (cnt > 0) { mean_m += (float)cnt * rv; max_m = fmaxf(max_m, rv); }
        }
        mean_m = __fdiv_rn(mean_m, Nf);
        if (max_m > 0.f) {
            float w2 = max_m - mean_m; w2 *= w2;   // min_m == 0 always
#pragma unroll
            for (int j = 0; j < 6; j++)
                lut[j] = __fmul_rn(__fdiv_rn(dn[j] * w1, max_m), w2);
        }
    }
#pragma unroll
    for (int j = 0; j < 6; j++) g_dlut[ch][j] = lut[j] - lut[5];
    g_dlut[ch][6] = lut[5];
    g_dlut[ch][7] = 0.f;
    if (first) g_border[layer] = lut[jb];
}

// ---------------- pass C: proc = sum_c lut_c[gidx_c] (vectorized) ----------------
template <int LAYER, int H, int C, int CB, long long GB, int PB, int PX>
__device__ void procN(int chunk, float* sdlut, float* ssum, float* sred) {
    constexpr int W = H, HW = H * W, NCH = HW / PX;
    for (int i = threadIdx.x; i < C * 8; i += THREADS)
        sdlut[i] = ((const float*)g_dlut[CB])[i];
    __syncthreads();
    // deterministic block-local S5 = sum_c lut_c[5]
    float s5p = 0.f;
    for (int c = threadIdx.x; c < C; c += THREADS) s5p += sdlut[c * 8 + 6];
#pragma unroll
    for (int o = 16; o; o >>= 1) s5p += __shfl_xor_sync(0xFFFFFFFFu, s5p, o);
    if ((threadIdx.x & 31) == 0) ssum[threadIdx.x >> 5] = s5p;
    __syncthreads();
    float S5 = 0.f;
#pragma unroll
    for (int i = 0; i < 8; i++) S5 += ssum[i];

    float bord = g_border[LAYER];
    float vmn = bord, vmx = bord;
    if (chunk < NCH) {
        float acc[PX];
#pragma unroll
        for (int k = 0; k < PX; k++) acc[k] = S5;
        long long base = GB + (long long)chunk * PX;
#pragma unroll 2
        for (int ch = 0; ch < C; ch++) {
            const unsigned char* p = g_gidx + base + (long long)ch * HW;
            int lb = ch * 8;
            if (PX == 16) {
                uint4 w = *(const uint4*)p;
                unsigned ws[4] = {w.x, w.y, w.z, w.w};
#pragma unroll
                for (int q = 0; q < 4; q++)
#pragma unroll
                    for (int t = 0; t < 4; t++)
                        acc[q * 4 + t] += sdlut[lb + ((ws[q] >> (8 * t)) & 7)];
            } else if (PX == 8) {
                uint2 w = *(const uint2*)p;
                unsigned ws[2] = {w.x, w.y};
#pragma unroll
                for (int q = 0; q < 2; q++)
#pragma unroll
                    for (int t = 0; t < 4; t++)
                        acc[q * 4 + t] += sdlut[lb + ((ws[q] >> (8 * t)) & 7)];
            } else if (PX == 4) {
                unsigned w = *(const unsigned*)p;
#pragma unroll
                for (int t = 0; t < 4; t++)
                    acc[t] += sdlut[lb + ((w >> (8 * t)) & 7)];
            } else if (PX == 2) {
                unsigned short w = *(const unsigned short*)p;
                acc[0] += sdlut[lb + (w & 7)];
                acc[1] += sdlut[lb + ((w >> 8) & 7)];
            } else {
                acc[0] += sdlut[lb + (p[0] & 7)];
            }
        }
        int p0 = chunk * PX;
        int r = p0 / W, c = p0 - r * W;
#pragma unroll
        for (int k = 0; k < PX; k++) {
            bool bd = ((unsigned)(r - 1) >= (unsigned)(H - 2)) ||
                      ((unsigned)(c - 1) >= (unsigned)(W - 2));
            float val = bd ? bord : acc[k];
            g_proc[PB + p0 + k] = val;
            vmn = fminf(vmn, val); vmx = fmaxf(vmx, val);
            if (++c == W) { c = 0; r++; }
        }
    }
    blockMinMax(vmn, vmx, g_pstat[LAYER], sred);
}

// blocks: l0:57(16px) l1:29(8px) l2:15(4px) l3:8(2px) l4:4(1px) -> 113
__global__ void __launch_bounds__(THREADS) k_proc() {
    __shared__ float sdlut[4096];
    __shared__ float ssum[8];
    __shared__ float sred[16];
    int b = blockIdx.x, t = threadIdx.x;
    if (b < 57)       procN<0, 480, 64, 0, 0LL, 0, 16>(b * THREADS + t, sdlut, ssum, sred);
    else if (b < 86)  procN<1, 240, 128, 64, 14745600LL, 230400, 8>((b - 57) * THREADS + t, sdlut, ssum, sred);
    else if (b < 101) procN<2, 120, 256, 192, 22118400LL, 288000, 4>((b - 86) * THREADS + t, sdlut, ssum, sred);
    else if (b < 109) procN<3, 60, 512, 448, 25804800LL, 302400, 2>((b - 101) * THREADS + t, sdlut, ssum, sred);
    else              procN<4, 30, 512, 960, 27648000LL, 306000, 1>((b - 109) * THREADS + t, sdlut, ssum, sred);
}

// ---------------- pass E: normalize+threshold (fused) + resize + group min/max ----
__device__ __forceinline__ float fth(float v, float mnp, float rng) {
    float pn = (rng == 0.f) ? 0.f : __fdiv_rn(v - mnp, rng);
    return (pn < 0.2f) ? 0.f : pn;
}

__global__ void __launch_bounds__(THREADS) k_resize() {
    __shared__ float sred[16];
    int b = blockIdx.x;
    int layer = b / 225;
    int p = (b - layer * 225) * THREADS + threadIdx.x;   // < 57600 exactly
    int y = p / 240, x = p % 240;
    float mnp = fdec(g_pstat[layer][0]);
    float mxp = fdec(g_pstat[layer][1]);
    float rng = mxp - mnp;
    float val;
    if (layer == 0) {
        // 480 -> 240 antialiased: taps [1,3,3,1]/8, edge-renormalized
        const float w4[4] = {1.f, 3.f, 3.f, 1.f};
        float wxs = 0.f;
#pragma unroll
        for (int j = 0; j < 4; j++) { int tx = 2 * x - 1 + j; if (tx >= 0 && tx < 480) wxs += w4[j]; }
        float acc = 0.f, wys = 0.f;
#pragma unroll
        for (int a = 0; a < 4; a++) {
            int ty = 2 * y - 1 + a;
            if (ty < 0 || ty > 479) continue;
            wys += w4[a];
            const float* row = g_proc + ty * 480;
            float ra = 0.f;
#pragma unroll
            for (int j = 0; j < 4; j++) {
                int tx = 2 * x - 1 + j;
                if (tx >= 0 && tx < 480) ra += w4[j] * fth(row[tx], mnp, rng);
            }
            acc += w4[a] * ra;
        }
        val = acc / (wys * wxs);
    } else if (layer == 1) {
        val = fth(g_proc[230400 + p], mnp, rng);         // identity resize
    } else {
        int H = layer == 2 ? 120 : layer == 3 ? 60 : 30;
        int base = layer == 2 ? 288000 : layer == 3 ? 302400 : 306000;
        const float* pr = g_proc + base;
        float s = (float)H / 240.f;                      // 0.5 / 0.25 / 0.125 exact
        float cy = (y + 0.5f) * s - 0.5f;
        float cx = (x + 0.5f) * s - 0.5f;
        float fly = floorf(cy), flx = floorf(cx);
        float fy = cy - fly, fx = cx - flx;
        int iy = (int)fly, ix = (int)flx;
        int y0 = max(iy, 0), y1 = min(iy + 1, H - 1);
        int x0 = max(ix, 0), x1 = min(ix + 1, H - 1);
        float a = fth(pr[y0 * H + x0], mnp, rng), bv = fth(pr[y0 * H + x1], mnp, rng);
        float c = fth(pr[y1 * H + x0], mnp, rng), d = fth(pr[y1 * H + x1], mnp, rng);
        val = (1.f - fy) * ((1.f - fx) * a + fx * bv) + fy * ((1.f - fx) * c + fx * d);
    }
    g_group[layer][p] = val;
    blockMinMax(val, val, g_gstat[layer], sred);
}

// ---------------- pass F: group normalize(0,256), write groups + sum ----------------
__global__ void __launch_bounds__(THREADS) k_final(float* __restrict__ out, int out_size) {
    int p = blockIdx.x * THREADS + threadIdx.x;          // 225 blocks * 256 = 57600 exactly
    float s = 0.f;
#pragma unroll
    for (int g = 0; g < 5; g++) {
        float mn = fdec(g_gstat[g][0]);
        float mx = fdec(g_gstat[g][1]);
        float rng = mx - mn;
        float v = g_group[g][p];
        float gv = (rng == 0.f) ? 0.f : __fmul_rn(__fdiv_rn(v - mn, rng), 256.f);
        if (out_size >= 345600) out[57600 + p * 5 + g] = gv;
        s += gv;
    }
    out[p] = s;
}

// ---------------- launch ----------------
extern "C" void kernel_launch(void* const* d_in, const int* in_sizes, int n_in,
                              void* d_out, int out_size) {
    const int want[5] = {14745600, 7372800, 3686400, 1843200, 460800};
    const float* L[5] = {nullptr, nullptr, nullptr, nullptr, nullptr};
    for (int i = 0; i < n_in && i < 16; i++)
        for (int j = 0; j < 5; j++)
            if (in_sizes[i] == want[j] && L[j] == nullptr) { L[j] = (const float*)d_in[i]; break; }
    for (int j = 0; j < 5; j++) if (!L[j] && j < n_in) L[j] = (const float*)d_in[j];

    k_init<<<69, THREADS>>>();
    k_minmax<<<2816, THREADS>>>(L[0], L[1], L[2], L[3], L[4]);
    k_hist<<<2816, THREADS>>>(L[0], L[1], L[2], L[3], L[4]);
    k_lut<<<6, THREADS>>>();
    k_proc<<<113, THREADS>>>();
    k_resize<<<1125, THREADS>>>();
    k_final<<<225, THREADS>>>((float*)d_out, out_size);
}

// round 5
// speedup vs baseline: 2.1491x; 1.9825x over previous
#include <cuda_runtime.h>
#include <math.h>
#include <stdint.h>

#define THREADS 256

// ---------------- layer tables ----------------
__constant__ int c_H[5]        = {480, 240, 120, 60, 30};
__constant__ int c_chanBase[5] = {0, 64, 192, 448, 960};
__constant__ int c_procBase[5] = {0, 230400, 288000, 302400, 306000};

// ---------------- scratch (device globals; no allocation) ----------------
__device__ unsigned g_cmax[1472];        // raw bits of per-channel max (values >= 0)
__device__ int      g_hist[1472][12];    // [0:6) histc bins, [6:12) gidx bins (j<5 + border)
__device__ float    g_lut[1472][6];      // per-channel contribution LUT
__device__ float    g_S5[5];             // sum_c lut_c[5] per layer
__device__ float    g_bord[5];           // border proc value per layer
__device__ unsigned g_rarecnt;
__device__ unsigned g_rare[28108800];    // packed rare records: pix|ch<<18|b2<<29
__device__ float    g_proc[306900];      // per-layer proc maps (raw, pre-threshold)
__device__ unsigned g_pstat[5][2];       // proc min/max per layer (encoded)
__device__ float    g_group[5][57600];   // resized+thresholded maps
__device__ unsigned g_gstat[5][2];       // group min/max per layer (encoded)

// ---------------- float <-> orderable uint ----------------
__device__ __forceinline__ unsigned fenc(float f) {
    unsigned b = __float_as_uint(f);
    return (b & 0x80000000u) ? ~b : (b | 0x80000000u);
}
__device__ __forceinline__ float fdec(unsigned u) {
    unsigned b = (u & 0x80000000u) ? (u & 0x7FFFFFFFu) : ~u;
    return __uint_as_float(b);
}

__device__ __forceinline__ void blockMinMax(float vmn, float vmx, unsigned* stat, float* s) {
#pragma unroll
    for (int o = 16; o; o >>= 1) {
        vmn = fminf(vmn, __shfl_xor_sync(0xFFFFFFFFu, vmn, o));
        vmx = fmaxf(vmx, __shfl_xor_sync(0xFFFFFFFFu, vmx, o));
    }
    int w = threadIdx.x >> 5;
    if ((threadIdx.x & 31) == 0) { s[w] = vmn; s[8 + w] = vmx; }
    __syncthreads();
    if (threadIdx.x == 0) {
        float a = s[0], b = s[8];
#pragma unroll
        for (int i = 1; i < 8; i++) { a = fminf(a, s[i]); b = fmaxf(b, s[8 + i]); }
        atomicMin(&stat[0], fenc(a));
        atomicMax(&stat[1], fenc(b));
    }
    __syncthreads();
}

// ---------------- pass 0: init ----------------
__global__ void __launch_bounds__(THREADS) k_init() {
    int i = blockIdx.x * THREADS + threadIdx.x;
    if (i < 1472 * 12) ((int*)g_hist)[i] = 0;
    if (i < 1472) g_cmax[i] = 0u;
    if (i == 0) g_rarecnt = 0u;
    if (i < 5) {
        g_pstat[i][0] = 0xFFFFFFFFu; g_pstat[i][1] = 0u;
        g_gstat[i][0] = 0xFFFFFFFFu; g_gstat[i][1] = 0u;
    }
}

// ---------------- block decode for passes A/B ----------------
// tiles per channel: {16,4,1,1,1}; blocks per layer {1024,512,256,512,512}; total 2816
struct BlkInfo { int layer, cloc, tile; };
__device__ __forceinline__ BlkInfo decodeAB(int b) {
    BlkInfo r;
    if (b < 1024)      { r.layer = 0; r.cloc = b >> 4;            r.tile = b & 15; }
    else if (b < 1536) { int t = b - 1024; r.layer = 1; r.cloc = t >> 2; r.tile = t & 3; }
    else if (b < 1792) { r.layer = 2; r.cloc = b - 1536; r.tile = 0; }
    else if (b < 2304) { r.layer = 3; r.cloc = b - 1792; r.tile = 0; }
    else               { r.layer = 4; r.cloc = b - 2304; r.tile = 0; }
    return r;
}

// ---------------- pass A: per-channel interior MAX (min is exactly 0) ----------------
template <int H, int T>
__device__ __forceinline__ float mxv_body(const float* __restrict__ base, int tile) {
    constexpr int W = H, F4 = W / 4;
    int rowsThis = (H - 2 - tile + T - 1) / T;
    int total = rowsThis * F4;
    float mx = 0.f;
    for (int i = threadIdx.x; i < total; i += THREADS) {
        int m = i / F4, j = i - m * F4;
        int r = 1 + tile + m * T;
        float4 v = *(const float4*)(base + r * W + 4 * j);
        if (j == 0) v.x = 0.f;
        if (j == F4 - 1) v.w = 0.f;
        mx = fmaxf(mx, fmaxf(fmaxf(v.x, v.y), fmaxf(v.z, v.w)));
    }
    return mx;
}
template <int H>
__device__ __forceinline__ float mxs_body(const float* __restrict__ base) {
    constexpr int W = H, IW = W - 2, NI = IW * (H - 2);
    float mx = 0.f;
    for (int i = threadIdx.x; i < NI; i += THREADS) {
        int q = i / IW, col = i - q * IW;
        mx = fmaxf(mx, base[(q + 1) * W + col + 1]);
    }
    return mx;
}

__global__ void __launch_bounds__(THREADS) k_max(const float* __restrict__ p0, const float* __restrict__ p1,
                                                 const float* __restrict__ p2, const float* __restrict__ p3,
                                                 const float* __restrict__ p4) {
    __shared__ float sred[8];
    BlkInfo bi = decodeAB(blockIdx.x);
    float mx; int ch;
    switch (bi.layer) {
        case 0: ch = bi.cloc;       mx = mxv_body<480, 16>(p0 + (long long)bi.cloc * 230400, bi.tile); break;
        case 1: ch = 64 + bi.cloc;  mx = mxv_body<240, 4>(p1 + (long long)bi.cloc * 57600, bi.tile); break;
        case 2: ch = 192 + bi.cloc; mx = mxv_body<120, 1>(p2 + (long long)bi.cloc * 14400, bi.tile); break;
        case 3: ch = 448 + bi.cloc; mx = mxv_body<60, 1>(p3 + (long long)bi.cloc * 3600, bi.tile); break;
        default: ch = 960 + bi.cloc; mx = mxs_body<30>(p4 + (long long)bi.cloc * 900); break;
    }
#pragma unroll
    for (int o = 16; o; o >>= 1) mx = fmaxf(mx, __shfl_xor_sync(0xFFFFFFFFu, mx, o));
    if ((threadIdx.x & 31) == 0) sred[threadIdx.x >> 5] = mx;
    __syncthreads();
    if (threadIdx.x == 0) {
        float a = sred[0];
#pragma unroll
        for (int i = 1; i < 8; i++) a = fmaxf(a, sred[i]);
        atomicMax(&g_cmax[ch], __float_as_uint(a));   // nonneg floats: raw-bit monotonic
    }
}

// ---------------- pass B: histc hist + rare-pixel emission ----------------
// i1 = floor(v * 1536/mx); b1 = min(i1>>8,5) (histc bin); rare iff i1<6 (gidx<5)
__device__ __forceinline__ void hist_flush1(unsigned long long h1, int ch) {
#pragma unroll
    for (int j = 0; j < 6; j++) {
        int c1 = (int)((h1 >> (j * 10)) & 1023u);
        c1 = __reduce_add_sync(0xFFFFFFFFu, c1);
        if ((threadIdx.x & 31) == 0 && c1) atomicAdd(&g_hist[ch][j], c1);
    }
}

__device__ __forceinline__ void rare_emit(bool rr, unsigned rec, int ch, int b2) {
    unsigned m = __ballot_sync(0xFFFFFFFFu, rr);
    if (m) {
        int ldr = __ffs(m) - 1;
        unsigned base;
        if ((threadIdx.x & 31) == ldr) base = atomicAdd(&g_rarecnt, (unsigned)__popc(m));
        base = __shfl_sync(0xFFFFFFFFu, base, ldr);
        if (rr) {
            unsigned off = base + __popc(m & ((1u << (threadIdx.x & 31)) - 1u));
            g_rare[off] = rec;
            atomicAdd(&g_hist[ch][6 + b2], 1);
        }
    }
}

template <int H, int T>
__device__ void histv_body(const float* __restrict__ base, int tile, int ch) {
    constexpr int W = H, F4 = W / 4;
    float mx = __uint_as_float(g_cmax[ch]);
    float s = (mx > 0.f) ? __fdiv_rn(1536.f, mx) : 0.f;
    unsigned long long h1 = 0ULL;
    int rowsThis = (H - 2 - tile + T - 1) / T;
    int total = rowsThis * F4;
    int iters = (total + THREADS - 1) / THREADS;
    for (int it = 0; it < iters; it++) {
        int i = it * THREADS + threadIdx.x;
        bool ok = i < total;
        int ii = ok ? i : 0;
        int m = ii / F4, j = ii - m * F4;
        int r = 1 + tile + m * T;
        float4 v = ok ? *(const float4*)(base + r * W + 4 * j)
                      : make_float4(0.f, 0.f, 0.f, 0.f);
        if (j == 0) v.x = 0.f;
        if (j == F4 - 1) v.w = 0.f;
        int i1[4];
        i1[0] = __float2int_rd(__fmul_rn(v.x, s));
        i1[1] = __float2int_rd(__fmul_rn(v.y, s));
        i1[2] = __float2int_rd(__fmul_rn(v.z, s));
        i1[3] = __float2int_rd(__fmul_rn(v.w, s));
        if (ok) {
#pragma unroll
            for (int k = 0; k < 4; k++) h1 += 1ULL << (min(i1[k] >> 8, 5) * 10);
        }
        unsigned pix = (unsigned)(r * W + 4 * j);
#pragma unroll
        for (int k = 0; k < 4; k++) {
            bool rr = ok && (i1[k] < 6);
            if (k == 0) rr = rr && (j != 0);          // border col 0 handled analytically
            if (k == 3) rr = rr && (j != F4 - 1);     // border col W-1
            int b2 = max(i1[k] - 1, 0);               // <= 4 whenever rr
            rare_emit(rr, (pix + k) | ((unsigned)ch << 18) | ((unsigned)b2 << 29), ch, b2);
        }
    }
    hist_flush1(h1, ch);
    if (tile == 0 && threadIdx.x == 0) {
        atomicAdd(&g_hist[ch][0], 2 * W);                 // rows 0,H-1 -> histc bin 0
        atomicAdd(&g_hist[ch][6 + 0], 2 * (H + W) - 4);   // full border -> gidx bin 0
    }
}

template <int H>
__device__ void hists_body(const float* __restrict__ base, int ch, int layer) {
    constexpr int W = H, IW = W - 2, NI = IW * (H - 2);
    float mx = __uint_as_float(g_cmax[ch]);
    float s = (mx > 0.f) ? __fdiv_rn(1536.f, mx) : 0.f;
    unsigned long long h1 = 0ULL;
    int iters = (NI + THREADS - 1) / THREADS;
    for (int it = 0; it < iters; it++) {
        int i = it * THREADS + threadIdx.x;
        bool ok = i < NI;
        int ii = ok ? i : 0;
        int q = ii / IW, col = ii - q * IW;
        int pix = (q + 1) * W + col + 1;
        float v = ok ? base[pix] : 1e30f;
        int i1 = __float2int_rd(__fmul_rn(v, s));
        if (ok) h1 += 1ULL << (min(i1 >> 8, 5) * 10);
        bool rr = ok && (i1 < 6);
        int b2 = max(i1 - 1, 0);
        rare_emit(rr, (unsigned)pix | ((unsigned)ch << 18) | ((unsigned)b2 << 29), ch, b2);
    }
    hist_flush1(h1, ch);
    if (threadIdx.x == 0) {
        int Nb = 2 * (H + W) - 4;
        atomicAdd(&g_hist[ch][0], Nb);
        atomicAdd(&g_hist[ch][6 + 0], Nb);
    }
}

__global__ void __launch_bounds__(THREADS) k_hist(const float* __restrict__ p0, const float* __restrict__ p1,
                                                  const float* __restrict__ p2, const float* __restrict__ p3,
                                                  const float* __restrict__ p4) {
    BlkInfo bi = decodeAB(blockIdx.x);
    switch (bi.layer) {
        case 0: histv_body<480, 16>(p0 + (long long)bi.cloc * 230400, bi.tile, bi.cloc); break;
        case 1: histv_body<240, 4>(p1 + (long long)bi.cloc * 57600, bi.tile, 64 + bi.cloc); break;
        case 2: histv_body<120, 1>(p2 + (long long)bi.cloc * 14400, bi.tile, 192 + bi.cloc); break;
        case 3: histv_body<60, 1>(p3 + (long long)bi.cloc * 3600, bi.tile, 448 + bi.cloc); break;
        default: hists_body<30>(p4 + (long long)bi.cloc * 900, 960 + bi.cloc, 4); break;
    }
}

// ---------------- pass LUT: per-channel 6-entry contribution table ----------------
__global__ void __launch_bounds__(32) k_lut() {
    int ch = blockIdx.x * 32 + threadIdx.x;
    if (ch >= 1472) return;
    int layer = ch < 64 ? 0 : ch < 192 ? 1 : ch < 448 ? 2 : ch < 960 ? 3 : 4;
    int H = c_H[layer], W = H, HW = H * W;
    float Nf = (float)HW;

    int gg[6], sg = 0;
#pragma unroll
    for (int j = 0; j < 5; j++) { gg[j] = g_hist[ch][6 + j]; sg += gg[j]; }
    gg[5] = HW - sg;                          // all non-rare interior pixels have gidx 5

    float hv[6];
#pragma unroll
    for (int j = 0; j < 6; j++)
        hv[j] = -logf(__fdiv_rn((float)g_hist[ch][j], Nf) + 1e-4f);

    float minv = 1e30f, maxv = -1e30f;
#pragma unroll
    for (int j = 0; j < 6; j++)
        if (gg[j] > 0) { minv = fminf(minv, hv[j]); maxv = fmaxf(maxv, hv[j]); }
    float rh = maxv - minv;

    const int jb = 0;                          // border pixels (value 0) -> gidx bin 0
    bool first = (ch == c_chanBase[layer]);    // channel 0 keeps its border in the map

    float lut[6] = {0.f, 0.f, 0.f, 0.f, 0.f, 0.f};
    if (rh > 0.f) {
        float dn[6];
#pragma unroll
        for (int j = 0; j < 6; j++)
            dn[j] = (gg[j] > 0) ? __fdiv_rn(hv[j] - minv, rh) : 0.f;
        float meandn = 0.f;
#pragma unroll
        for (int j = 0; j < 6; j++) meandn += (float)gg[j] * dn[j];
        meandn = __fdiv_rn(meandn, Nf);
        float w1 = 1.f - meandn; w1 *= w1;     // (max_dst - mean_dst)^2, max_dst == 1
        int Nb = 2 * (H + W) - 4;
        float mean_m = 0.f;
        float max_m = first ? -1e30f : 0.f;    // zeroed border contributes 0 for c>=1
#pragma unroll
        for (int j = 0; j < 6; j++) {
            int cnt = gg[j] - ((!first && j == jb) ? Nb : 0);
            float rv = dn[j] * w1;
            if (cnt > 0) { mean_m += (float)cnt * rv; max_m = fmaxf(max_m, rv); }
        }
        mean_m = __fdiv_rn(mean_m, Nf);
        if (max_m > 0.f) {
            float w2 = max_m - mean_m; w2 *= w2;   // min_m == 0 always
#pragma unroll
            for (int j = 0; j < 6; j++)
                lut[j] = __fmul_rn(__fdiv_rn(dn[j] * w1, max_m), w2);
        }
    }
#pragma unroll
    for (int j = 0; j < 6; j++) g_lut[ch][j] = lut[j];
}

// ---------------- pass S5: per-layer sum of lut[5] + border value ----------------
__global__ void __launch_bounds__(THREADS) k_s5() {
    __shared__ float sh[THREADS];
    int l = blockIdx.x;
    int C = (l == 0) ? 64 : (l == 1) ? 128 : (l == 2) ? 256 : 512;
    int cb = c_chanBase[l];
    float s = 0.f;
    for (int c = threadIdx.x; c < C; c += THREADS) s += g_lut[cb + c][5];
    sh[threadIdx.x] = s;
    __syncthreads();
    for (int st = THREADS / 2; st; st >>= 1) {
        if (threadIdx.x < st) sh[threadIdx.x] += sh[threadIdx.x + st];
        __syncthreads();
    }
    if (threadIdx.x == 0) { g_S5[l] = sh[0]; g_bord[l] = g_lut[cb][0]; }
}

// ---------------- pass fill: proc = S5 interior, bord on borders ----------------
__global__ void __launch_bounds__(THREADS) k_fill() {
    int i = blockIdx.x * THREADS + threadIdx.x;
    if (i >= 306900) return;
    int layer = i < 230400 ? 0 : i < 288000 ? 1 : i < 302400 ? 2 : i < 306000 ? 3 : 4;
    int W = c_H[layer];
    int p = i - c_procBase[layer];
    int r = p / W, c = p - r * W;
    bool bd = (r == 0) | (c == 0) | (r == W - 1) | (c == W - 1);
    g_proc[i] = bd ? g_bord[layer] : g_S5[layer];
}

// ---------------- pass scatter: apply rare corrections ----------------
__global__ void __launch_bounds__(THREADS) k_scatter() {
    unsigned n = g_rarecnt;
    for (unsigned i = blockIdx.x * THREADS + threadIdx.x; i < n; i += gridDim.x * THREADS) {
        unsigned e = g_rare[i];
        unsigned pix = e & 0x3FFFFu;
        unsigned ch  = (e >> 18) & 0x7FFu;
        unsigned b2  = e >> 29;
        int layer = ch < 64 ? 0 : ch < 192 ? 1 : ch < 448 ? 2 : ch < 960 ? 3 : 4;
        float d = g_lut[ch][b2] - g_lut[ch][5];
        atomicAdd(&g_proc[c_procBase[layer] + pix], d);
    }
}

// ---------------- pass pstat: per-layer proc min/max ----------------
// blocks: l0:900 l1:225 l2:57 l3:15 l4:4 -> 1201
__global__ void __launch_bounds__(THREADS) k_pstat() {
    __shared__ float sred[16];
    int b = blockIdx.x;
    int layer, loc;
    if (b < 900)       { layer = 0; loc = b; }
    else if (b < 1125) { layer = 1; loc = b - 900; }
    else if (b < 1182) { layer = 2; loc = b - 1125; }
    else if (b < 1197) { layer = 3; loc = b - 1182; }
    else               { layer = 4; loc = b - 1197; }
    int H = c_H[layer], HW = H * H, pb = c_procBase[layer];
    int p = loc * THREADS + threadIdx.x;
    float val = g_proc[pb + ((p < HW) ? p : 0)];
    blockMinMax(val, val, g_pstat[layer], sred);
}

// ---------------- pass E: normalize+threshold (fused) + resize + group min/max ----
__device__ __forceinline__ float fth(float v, float mnp, float rng) {
    float pn = (rng == 0.f) ? 0.f : __fdiv_rn(v - mnp, rng);
    return (pn < 0.2f) ? 0.f : pn;
}

__global__ void __launch_bounds__(THREADS) k_resize() {
    __shared__ float sred[16];
    int b = blockIdx.x;
    int layer = b / 225;
    int p = (b - layer * 225) * THREADS + threadIdx.x;   // < 57600 exactly
    int y = p / 240, x = p % 240;
    float mnp = fdec(g_pstat[layer][0]);
    float mxp = fdec(g_pstat[layer][1]);
    float rng = mxp - mnp;
    float val;
    if (layer == 0) {
        // 480 -> 240 antialiased: taps [1,3,3,1]/8, edge-renormalized
        const float w4[4] = {1.f, 3.f, 3.f, 1.f};
        float wxs = 0.f;
#pragma unroll
        for (int j = 0; j < 4; j++) { int tx = 2 * x - 1 + j; if (tx >= 0 && tx < 480) wxs += w4[j]; }
        float acc = 0.f, wys = 0.f;
#pragma unroll
        for (int a = 0; a < 4; a++) {
            int ty = 2 * y - 1 + a;
            if (ty < 0 || ty > 479) continue;
            wys += w4[a];
            const float* row = g_proc + ty * 480;
            float ra = 0.f;
#pragma unroll
            for (int j = 0; j < 4; j++) {
                int tx = 2 * x - 1 + j;
                if (tx >= 0 && tx < 480) ra += w4[j] * fth(row[tx], mnp, rng);
            }
            acc += w4[a] * ra;
        }
        val = acc / (wys * wxs);
    } else if (layer == 1) {
        val = fth(g_proc[230400 + p], mnp, rng);         // identity resize
    } else {
        int H = layer == 2 ? 120 : layer == 3 ? 60 : 30;
        int base = layer == 2 ? 288000 : layer == 3 ? 302400 : 306000;
        const float* pr = g_proc + base;
        float s = (float)H / 240.f;                      // 0.5 / 0.25 / 0.125 exact
        float cy = (y + 0.5f) * s - 0.5f;
        float cx = (x + 0.5f) * s - 0.5f;
        float fly = floorf(cy), flx = floorf(cx);
        float fy = cy - fly, fx = cx - flx;
        int iy = (int)fly, ix = (int)flx;
        int y0 = max(iy, 0), y1 = min(iy + 1, H - 1);
        int x0 = max(ix, 0), x1 = min(ix + 1, H - 1);
        float a = fth(pr[y0 * H + x0], mnp, rng), bv = fth(pr[y0 * H + x1], mnp, rng);
        float c = fth(pr[y1 * H + x0], mnp, rng), d = fth(pr[y1 * H + x1], mnp, rng);
        val = (1.f - fy) * ((1.f - fx) * a + fx * bv) + fy * ((1.f - fx) * c + fx * d);
    }
    g_group[layer][p] = val;
    blockMinMax(val, val, g_gstat[layer], sred);
}

// ---------------- pass F: group normalize(0,256), write groups + sum ----------------
__global__ void __launch_bounds__(THREADS) k_final(float* __restrict__ out, int out_size) {
    int p = blockIdx.x * THREADS + threadIdx.x;          // 225 blocks * 256 = 57600 exactly
    float s = 0.f;
#pragma unroll
    for (int g = 0; g < 5; g++) {
        float mn = fdec(g_gstat[g][0]);
        float mx = fdec(g_gstat[g][1]);
        float rng = mx - mn;
        float v = g_group[g][p];
        float gv = (rng == 0.f) ? 0.f : __fmul_rn(__fdiv_rn(v - mn, rng), 256.f);
        if (out_size >= 345600) out[57600 + p * 5 + g] = gv;
        s += gv;
    }
    out[p] = s;
}

// ---------------- launch ----------------
extern "C" void kernel_launch(void* const* d_in, const int* in_sizes, int n_in,
                              void* d_out, int out_size) {
    const int want[5] = {14745600, 7372800, 3686400, 1843200, 460800};
    const float* L[5] = {nullptr, nullptr, nullptr, nullptr, nullptr};
    for (int i = 0; i < n_in && i < 16; i++)
        for (int j = 0; j < 5; j++)
            if (in_sizes[i] == want[j] && L[j] == nullptr) { L[j] = (const float*)d_in[i]; break; }
    for (int j = 0; j < 5; j++) if (!L[j] && j < n_in) L[j] = (const float*)d_in[j];

    k_init<<<69, THREADS>>>();
    k_max<<<2816, THREADS>>>(L[0], L[1], L[2], L[3], L[4]);
    k_hist<<<2816, THREADS>>>(L[0], L[1], L[2], L[3], L[4]);
    k_lut<<<46, 32>>>();
    k_s5<<<5, THREADS>>>();
    k_fill<<<1199, THREADS>>>();
    k_scatter<<<128, THREADS>>>();
    k_pstat<<<1201, THREADS>>>();
    k_resize<<<1125, THREADS>>>();
    k_final<<<225, THREADS>>>((float*)d_out, out_size);
}